// round 2
// baseline (speedup 1.0000x reference)
#include <cuda_runtime.h>
#include <cub/cub.cuh>
#include <cstdint>

// Problem constants
#define BB 8
#define CC 21
#define HH 512
#define WW 512
#define HWW (HH * WW)            // 262144
#define PP (BB * HWW)            // 2097152 pixels
#define TILE 1024
#define NTILES (PP / TILE)       // 2048

// ---------------- scratch (static device globals; no allocation) -------------
__device__ unsigned int g_keys[(size_t)CC * PP];   // packed keys, all classes (176 MB)
__device__ __align__(256) unsigned int g_sorted[PP];       // sorted keys (8 MB)
__device__ __align__(256) unsigned char g_cubtemp[1u << 26]; // 64 MB cub temp
__device__ int    g_counts[CC];                    // G per class (label histogram)
__device__ int    g_tileSums[NTILES];
__device__ int    g_tileOffs[NTILES];              // exclusive scan of tile fg sums
__device__ double g_blockSums[NTILES];             // per-block loss partials
__device__ double g_loss;                          // accumulated over classes

// ---------------- kernels ----------------------------------------------------

__global__ void init_kernel() {
    int t = threadIdx.x;
    if (t < CC) g_counts[t] = 0;
    if (t == 0) g_loss = 0.0;
}

// Fused: per-pixel softmax over C, label histogram, write packed keys for all C
// key = (float_bits(err) << 1) | fg   (err in [0,1] => bits < 2^30 => fits 31b)
// NOTE: targets are int32 (JAX x64 disabled downgrades jnp.int64 -> int32).
__global__ void stats_keys_kernel(const float* __restrict__ x,
                                  const int* __restrict__ tgt) {
    __shared__ int sh_cnt[CC];
    if (threadIdx.x < CC) sh_cnt[threadIdx.x] = 0;
    __syncthreads();

    int p = blockIdx.x * blockDim.x + threadIdx.x;
    if (p < PP) {
        int b  = p / HWW;
        int hw = p - b * HWW;
        const float* base = x + ((size_t)b * CC) * HWW + hw;

        float v[CC];
        float m = -INFINITY;
#pragma unroll
        for (int c = 0; c < CC; c++) {
            v[c] = base[(size_t)c * HWW];
            m = fmaxf(m, v[c]);
        }
        float z = 0.0f;
#pragma unroll
        for (int c = 0; c < CC; c++) {
            v[c] = expf(v[c] - m);
            z += v[c];
        }
        float inv = 1.0f / z;
        int lbl = tgt[p];
        // crash-guard: clamp for the shared-histogram index (labels are 0..20)
        int lbl_c = min(max(lbl, 0), CC - 1);
        atomicAdd(&sh_cnt[lbl_c], 1);

#pragma unroll
        for (int c = 0; c < CC; c++) {
            float prob = v[c] * inv;
            unsigned fg = (lbl == c) ? 1u : 0u;
            float err = fg ? (1.0f - prob) : prob;     // err in [0,1]
            g_keys[(size_t)c * PP + p] = (__float_as_uint(err) << 1) | fg;
        }
    }
    __syncthreads();
    if (threadIdx.x < CC) atomicAdd(&g_counts[threadIdx.x], sh_cnt[threadIdx.x]);
}

// Per-tile fg counts over sorted keys
__global__ void tile_fg_kernel() {
    int gid = blockIdx.x * TILE + threadIdx.x;
    int f = (int)(g_sorted[gid] & 1u);
    typedef cub::BlockReduce<int, TILE> BR;
    __shared__ typename BR::TempStorage ts;
    int s = BR(ts).Sum(f);
    if (threadIdx.x == 0) g_tileSums[blockIdx.x] = s;
}

// Exclusive scan of NTILES tile sums (single block, 2 rounds of 1024)
__global__ void scan_tiles_kernel() {
    typedef cub::BlockScan<int, TILE> BS;
    __shared__ typename BS::TempStorage ts;
    __shared__ int carry;
    if (threadIdx.x == 0) carry = 0;
    __syncthreads();
#pragma unroll
    for (int it = 0; it < NTILES / TILE; ++it) {
        int i = it * TILE + threadIdx.x;
        int v = g_tileSums[i];
        int excl, agg;
        BS(ts).ExclusiveSum(v, excl, agg);
        g_tileOffs[i] = excl + carry;
        __syncthreads();
        if (threadIdx.x == 0) carry += agg;
        __syncthreads();
    }
}

// loss_c = sum_i J_i * (e_i - e_{i+1}),  J_i = 1 - (G - F_i) / (G + (i+1) - F_i)
__global__ void loss_kernel(int cls) {
    int gid = blockIdx.x * TILE + threadIdx.x;
    unsigned k = g_sorted[gid];
    int   f = (int)(k & 1u);
    float e = __uint_as_float(k >> 1);
    float en = (gid + 1 < PP) ? __uint_as_float(g_sorted[gid + 1] >> 1) : 0.0f;

    typedef cub::BlockScan<int, TILE> BS;
    __shared__ typename BS::TempStorage ts_scan;
    int F;
    BS(ts_scan).InclusiveSum(f, F);
    F += g_tileOffs[blockIdx.x];

    double G  = (double)g_counts[cls];
    double Fd = (double)F;
    double cnt = (double)gid + 1.0;
    double J = 1.0 - (G - Fd) / (G + cnt - Fd);
    double term = J * ((double)e - (double)en);

    typedef cub::BlockReduce<double, TILE> BRd;
    __shared__ typename BRd::TempStorage ts_red;
    double s = BRd(ts_red).Sum(term);
    if (threadIdx.x == 0) g_blockSums[blockIdx.x] = s;
}

// Deterministic reduction of per-block partials into g_loss
__global__ void reduce_loss_kernel() {
    double s = 0.0;
#pragma unroll
    for (int it = 0; it < NTILES / TILE; ++it)
        s += g_blockSums[it * TILE + threadIdx.x];
    typedef cub::BlockReduce<double, TILE> BRd;
    __shared__ typename BRd::TempStorage ts;
    double tot = BRd(ts).Sum(s);
    if (threadIdx.x == 0) g_loss += tot;
}

__global__ void final_kernel(float* out) {
    out[0] = (float)(g_loss / (double)CC);   // LOSS_WEIGHT = 1.0
}

// ---------------- launch ------------------------------------------------------

extern "C" void kernel_launch(void* const* d_in, const int* in_sizes, int n_in,
                              void* d_out, int out_size) {
    // inputs: B*C*H*W float32 (44040192 elems); targets: P int32 (2097152 elems)
    const float* x   = (const float*)d_in[0];
    const int*   tgt = (const int*)d_in[1];
    if (in_sizes[0] == PP) {  // swapped order safety
        x   = (const float*)d_in[1];
        tgt = (const int*)d_in[0];
    }
    float* out = (float*)d_out;

    void *keysAddr = nullptr, *sortedAddr = nullptr, *tempAddr = nullptr;
    cudaGetSymbolAddress(&keysAddr,   g_keys);
    cudaGetSymbolAddress(&sortedAddr, g_sorted);
    cudaGetSymbolAddress(&tempAddr,   g_cubtemp);
    if (!keysAddr || !sortedAddr || !tempAddr) return;  // should never happen

    init_kernel<<<1, 32>>>();
    stats_keys_kernel<<<(PP + 255) / 256, 256>>>(x, tgt);

    for (int c = 0; c < CC; c++) {
        size_t temp_bytes = sizeof(g_cubtemp);
        cub::DeviceRadixSort::SortKeysDescending(
            tempAddr, temp_bytes,
            (const unsigned int*)keysAddr + (size_t)c * PP,
            (unsigned int*)sortedAddr,
            PP, 0, 32);

        tile_fg_kernel<<<NTILES, TILE>>>();
        scan_tiles_kernel<<<1, TILE>>>();
        loss_kernel<<<NTILES, TILE>>>(c);
        reduce_loss_kernel<<<1, TILE>>>();
    }

    final_kernel<<<1, 1>>>(out);
}

// round 4
// speedup vs baseline: 5.7695x; 5.7695x over previous
#include <cuda_runtime.h>
#include <cub/cub.cuh>
#include <cstdint>

// Problem constants
#define BB 8
#define CC 21
#define HWW 262144                    // 512*512
#define PP 2097152                    // BB*HWW pixels per class
#define NTOT ((size_t)CC * (size_t)PP)  // 44040192 total keys
#define TPB 256
#define VPT 16
#define TILE (TPB * VPT)              // 4096
#define NT ((int)(NTOT / TILE))       // 10752 tiles
#define TILES_PER_CLASS (PP / TILE)   // 512

// ---------------- scratch (static device globals) ----------------------------
__device__ __align__(256) unsigned int g_keys[NTOT];    // 176 MB
__device__ __align__(256) unsigned int g_alt[NTOT];     // 176 MB (radix ping-pong)
__device__ __align__(256) unsigned char g_cubtemp[1u << 26];
__device__ int    g_counts[CC];
__device__ int    g_tileSums[NT];
__device__ int    g_tileOffs[NT];     // exclusive scan of tile fg sums, per class
__device__ float  g_blockSums[NT];    // per-block loss partials

// key layout (descending sort): [31:27]=cls  [26:1]=errbits>>4  [0]=fg
// decode: e = __uint_as_float(((key>>1) & 0x3FFFFFF) << 4)

// ---------------- kernels ----------------------------------------------------

__global__ void init_kernel() {
    if (threadIdx.x < CC) g_counts[threadIdx.x] = 0;
}

// Per-pixel softmax over C, label histogram, write packed keys for all C.
// targets are int32 (JAX without x64 downgrades jnp.int64 -> int32).
__global__ void stats_keys_kernel(const float* __restrict__ x,
                                  const int* __restrict__ tgt) {
    __shared__ int sh_cnt[CC];
    if (threadIdx.x < CC) sh_cnt[threadIdx.x] = 0;
    __syncthreads();

    int p = blockIdx.x * blockDim.x + threadIdx.x;  // p < PP always (PP % 256 == 0)
    {
        int b  = p / HWW;
        int hw = p - b * HWW;
        const float* base = x + ((size_t)b * CC) * HWW + hw;

        float v[CC];
        float m = -INFINITY;
#pragma unroll
        for (int c = 0; c < CC; c++) {
            v[c] = __ldg(base + (size_t)c * HWW);
            m = fmaxf(m, v[c]);
        }
        float z = 0.0f;
#pragma unroll
        for (int c = 0; c < CC; c++) {
            v[c] = __expf(v[c] - m);
            z += v[c];
        }
        float inv = 1.0f / z;
        int lbl = tgt[p];
        int lbl_c = min(max(lbl, 0), CC - 1);
        atomicAdd(&sh_cnt[lbl_c], 1);

#pragma unroll
        for (int c = 0; c < CC; c++) {
            float prob = v[c] * inv;
            unsigned fg = (lbl == c) ? 1u : 0u;
            float err = fg ? (1.0f - prob) : prob;         // [0,1]
            unsigned eb = __float_as_uint(err) >> 4;       // 26 bits
            g_keys[(size_t)c * PP + p] = ((unsigned)c << 27) | (eb << 1) | fg;
        }
    }
    __syncthreads();
    if (threadIdx.x < CC) atomicAdd(&g_counts[threadIdx.x], sh_cnt[threadIdx.x]);
}

// Phase A: per-tile fg counts over sorted keys (vectorized)
__global__ void tile_fg_kernel(const unsigned int* __restrict__ sorted) {
    size_t base = (size_t)blockIdx.x * TILE + (size_t)threadIdx.x * VPT;
    const uint4* v = (const uint4*)(sorted + base);
    int f = 0;
#pragma unroll
    for (int j = 0; j < VPT / 4; j++) {
        uint4 k = __ldg(v + j);
        f += (int)(k.x & 1u) + (int)(k.y & 1u) + (int)(k.z & 1u) + (int)(k.w & 1u);
    }
    typedef cub::BlockReduce<int, TPB> BR;
    __shared__ typename BR::TempStorage ts;
    int s = BR(ts).Sum(f);
    if (threadIdx.x == 0) g_tileSums[blockIdx.x] = s;
}

// Phase B: per-class exclusive scan of tile sums (21 blocks x 512 tiles each)
__global__ void scan_tiles_kernel() {
    int cls_seg = blockIdx.x;                 // 0..CC-1 (segment order)
    int i = cls_seg * TILES_PER_CLASS + threadIdx.x;
    int v = g_tileSums[i];
    typedef cub::BlockScan<int, TILES_PER_CLASS> BS;
    __shared__ typename BS::TempStorage ts;
    int excl;
    BS(ts).ExclusiveSum(v, excl);
    g_tileOffs[i] = excl;
}

// Phase C: loss partials.  J_i = n/(G + n - F_i),  term = J_i*(e_i - e_{i+1})
__global__ void loss_kernel(const unsigned int* __restrict__ sorted) {
    size_t base = (size_t)blockIdx.x * TILE + (size_t)threadIdx.x * VPT;
    unsigned k[VPT];
    const uint4* v = (const uint4*)(sorted + base);
#pragma unroll
    for (int j = 0; j < VPT / 4; j++) {
        uint4 q = __ldg(v + j);
        k[j * 4 + 0] = q.x; k[j * 4 + 1] = q.y; k[j * 4 + 2] = q.z; k[j * 4 + 3] = q.w;
    }
    int fsum = 0;
#pragma unroll
    for (int j = 0; j < VPT; j++) fsum += (int)(k[j] & 1u);

    typedef cub::BlockScan<int, TPB> BS;
    __shared__ typename BS::TempStorage ts_scan;
    int fbase;
    BS(ts_scan).ExclusiveSum(fsum, fbase);
    fbase += g_tileOffs[blockIdx.x];

    // class segment info (tiles never cross class boundaries: PP % TILE == 0)
    int seg = (int)(((size_t)blockIdx.x * TILE) / PP);
    int cls = (CC - 1) - seg;
    float G = (float)g_counts[cls];
    int i0 = (int)((size_t)blockIdx.x * TILE - (size_t)seg * PP) + (int)threadIdx.x * VPT;

    // next-key for the thread's last element
    size_t gnext = base + VPT;
    float elast_next = 0.0f;
    if ((gnext % PP) != 0) {   // class boundary (incl. global end) -> e_next = 0
        unsigned kn = __ldg(sorted + gnext);
        elast_next = __uint_as_float(((kn >> 1) & 0x3FFFFFFu) << 4);
    }

    float acc = 0.0f;
    int F = fbase;
#pragma unroll
    for (int j = 0; j < VPT; j++) {
        F += (int)(k[j] & 1u);                                   // inclusive
        float e  = __uint_as_float(((k[j] >> 1) & 0x3FFFFFFu) << 4);
        float en = (j + 1 < VPT)
                 ? __uint_as_float(((k[j + 1] >> 1) & 0x3FFFFFFu) << 4)
                 : elast_next;
        float n = (float)(i0 + j + 1);
        float J = n / (G + n - (float)F);
        acc += J * (e - en);
    }

    typedef cub::BlockReduce<float, TPB> BRf;
    __shared__ typename BRf::TempStorage ts_red;
    float s = BRf(ts_red).Sum(acc);
    if (threadIdx.x == 0) g_blockSums[blockIdx.x] = s;
}

// Final: deterministic f64 reduction of block partials -> mean over classes
__global__ void final_kernel(float* __restrict__ out) {
    double s = 0.0;
    for (int j = threadIdx.x; j < NT; j += blockDim.x)
        s += (double)g_blockSums[j];
    typedef cub::BlockReduce<double, 1024> BRd;
    __shared__ typename BRd::TempStorage ts;
    double tot = BRd(ts).Sum(s);
    if (threadIdx.x == 0) out[0] = (float)(tot / (double)CC);
}

// ---------------- launch ------------------------------------------------------

extern "C" void kernel_launch(void* const* d_in, const int* in_sizes, int n_in,
                              void* d_out, int out_size) {
    const float* x   = (const float*)d_in[0];
    const int*   tgt = (const int*)d_in[1];
    if (in_sizes[0] == PP) {  // swapped order safety
        x   = (const float*)d_in[1];
        tgt = (const int*)d_in[0];
    }
    float* out = (float*)d_out;

    void *keysAddr = nullptr, *altAddr = nullptr, *tempAddr = nullptr;
    cudaGetSymbolAddress(&keysAddr, g_keys);
    cudaGetSymbolAddress(&altAddr,  g_alt);
    cudaGetSymbolAddress(&tempAddr, g_cubtemp);
    if (!keysAddr || !altAddr || !tempAddr) return;

    init_kernel<<<1, 32>>>();
    stats_keys_kernel<<<PP / 256, 256>>>(x, tgt);

    // ONE descending radix sort of all 44M packed keys (class id in top bits)
    cub::DoubleBuffer<unsigned int> dbuf((unsigned int*)keysAddr,
                                         (unsigned int*)altAddr);
    size_t temp_bytes = sizeof(g_cubtemp);
    cub::DeviceRadixSort::SortKeysDescending(tempAddr, temp_bytes, dbuf,
                                             (int)NTOT, 0, 32);
    const unsigned int* sorted = dbuf.Current();

    tile_fg_kernel<<<NT, TPB>>>(sorted);
    scan_tiles_kernel<<<CC, TILES_PER_CLASS>>>();
    loss_kernel<<<NT, TPB>>>(sorted);
    final_kernel<<<1, 1024>>>(out);
}